// round 4
// baseline (speedup 1.0000x reference)
#include <cuda_runtime.h>
#include <math.h>

// Problem constants
#define B_    4
#define T_    2048
#define D_    1024
#define H_    16
#define HD_   64
#define FFN_  4096
#define ROWS_ (B_ * T_)        // 8192

// ---------------------------------------------------------------------------
// Scratch (device globals -- allocation inside kernel_launch is forbidden)
// ---------------------------------------------------------------------------
__device__ float g_x [ROWS_ * D_];    // LN1 output
__device__ float g_q [ROWS_ * D_];
__device__ float g_k [ROWS_ * D_];
__device__ float g_v [ROWS_ * D_];
__device__ float g_o [ROWS_ * D_];    // attention output
__device__ float g_h2[ROWS_ * D_];    // h + o@wo
__device__ float g_y [ROWS_ * D_];    // LN2 output
__device__ float g_a [ROWS_ * FFN_];  // y@w1  (then silu(a)*g in place)
__device__ float g_g [ROWS_ * FFN_];  // y@w2

// ---------------------------------------------------------------------------
// Helpers
// ---------------------------------------------------------------------------
__device__ __forceinline__ unsigned f2tf32(float x) {
    unsigned u;
    asm("cvt.rna.tf32.f32 %0, %1;" : "=r"(u) : "f"(x));
    return u;
}

__device__ __forceinline__ void mma_tf32(float c[4],
                                         unsigned a0, unsigned a1, unsigned a2, unsigned a3,
                                         unsigned b0, unsigned b1) {
    asm volatile(
        "mma.sync.aligned.m16n8k8.row.col.f32.tf32.tf32.f32 "
        "{%0,%1,%2,%3}, {%4,%5,%6,%7}, {%8,%9}, {%0,%1,%2,%3};"
        : "+f"(c[0]), "+f"(c[1]), "+f"(c[2]), "+f"(c[3])
        : "r"(a0), "r"(a1), "r"(a2), "r"(a3), "r"(b0), "r"(b1));
}

// ---------------------------------------------------------------------------
// LayerNorm: one block (256 threads) per row of 1024
// ---------------------------------------------------------------------------
__global__ void ln_kernel(const float* __restrict__ in,
                          const float* __restrict__ gam,
                          const float* __restrict__ bet,
                          float* __restrict__ out)
{
    __shared__ float r1[8], r2[8];
    __shared__ float s_mu, s_rstd;
    int row = blockIdx.x, tid = threadIdx.x;

    const float4* p = reinterpret_cast<const float4*>(in) + (size_t)row * (D_ / 4);
    float4 v = p[tid];
    float s  = v.x + v.y + v.z + v.w;
    float s2 = v.x * v.x + v.y * v.y + v.z * v.z + v.w * v.w;
    #pragma unroll
    for (int o = 16; o; o >>= 1) {
        s  += __shfl_xor_sync(0xffffffffu, s,  o);
        s2 += __shfl_xor_sync(0xffffffffu, s2, o);
    }
    if ((tid & 31) == 0) { r1[tid >> 5] = s; r2[tid >> 5] = s2; }
    __syncthreads();
    if (tid == 0) {
        float a = 0.f, b = 0.f;
        #pragma unroll
        for (int i = 0; i < 8; i++) { a += r1[i]; b += r2[i]; }
        float mu  = a / (float)D_;
        float var = b / (float)D_ - mu * mu;
        s_mu = mu;
        s_rstd = rsqrtf(var + 1e-5f);
    }
    __syncthreads();
    float mu = s_mu, rs = s_rstd;
    float4 g4 = reinterpret_cast<const float4*>(gam)[tid];
    float4 b4 = reinterpret_cast<const float4*>(bet)[tid];
    float4 o;
    o.x = (v.x - mu) * rs * g4.x + b4.x;
    o.y = (v.y - mu) * rs * g4.y + b4.y;
    o.z = (v.z - mu) * rs * g4.z + b4.z;
    o.w = (v.w - mu) * rs * g4.w + b4.w;
    reinterpret_cast<float4*>(out)[(size_t)row * (D_ / 4) + tid] = o;
}

// ---------------------------------------------------------------------------
// TF32 tensor-core GEMM, double-buffered.
// C[M,N] = A[M,K] @ W[K,N] (+R). Block 128x128, BK=16, 8 warps (4m x 2n),
// warp tile 32x64 via mma.m16n8k8 (2 mf x 8 nf).
// A smem: [k][m] stride 136 (conflict-free frag reads).
// B smem: packed uint2 {B[k][n], B[k+4][n]} at idx n*9 + kt*4 + qk (pad 9).
// NGEM selects W/C by blockIdx.z (QKV fusion).
// ---------------------------------------------------------------------------
#define SK_ 136
#define BSTR_ 9    // uint2 slots per n (8 used + 1 pad)

template <bool RES, int NGEM>
__global__ void __launch_bounds__(256, 2)
tgemm_kernel(const float* __restrict__ A,
             const float* __restrict__ W0, const float* __restrict__ W1,
             const float* __restrict__ W2,
             const float* __restrict__ R,
             float* __restrict__ C0, float* __restrict__ C1, float* __restrict__ C2,
             int M, int N, int K)
{
    __shared__ unsigned As[2][16 * SK_];          // [k][m]
    __shared__ unsigned Bs[2][128 * BSTR_ * 2];   // uint2-packed

    const float* W = W0;
    float* C = C0;
    if (NGEM == 3) {
        int z = blockIdx.z;
        W = (z == 0) ? W0 : (z == 1) ? W1 : W2;
        C = (z == 0) ? C0 : (z == 1) ? C1 : C2;
    }

    const int tid  = threadIdx.x;
    const int lane = tid & 31;
    const int warp = tid >> 5;
    const int wm   = (warp >> 1) * 32;   // warp m-offset
    const int wn   = (warp & 1) * 64;    // warp n-offset
    const int qm   = lane >> 2;          // 0..7
    const int qk   = lane & 3;           // 0..3

    const int bm = blockIdx.y * 128, bn = blockIdx.x * 128;

    // staging assignments
    const int arow = tid >> 1;             // 0..127
    const int akc  = (tid & 1) * 8;        // 0 or 8
    const int bkr  = tid >> 4;             // k row 0..15
    const int bnc  = (tid & 15) * 4;       // n 0..60

    // B pack coords for this staging thread (k fixed)
    const int bkt  = bkr >> 3;             // 0/1
    const int bqk  = bkr & 3;              // 0..3
    const int bkhi = (bkr >> 2) & 1;       // 0/1

    const float* Ap = A + (size_t)(bm + arow) * K + akc;
    const float* Bp = W + (size_t)bkr * N + bn + bnc;

    float acc[2][8][4];
    #pragma unroll
    for (int i = 0; i < 2; i++)
        #pragma unroll
        for (int j = 0; j < 8; j++)
            #pragma unroll
            for (int r = 0; r < 4; r++) acc[i][j][r] = 0.f;

    // ---- prologue: load tile 0, store to stage 0 ----
    float4 ra0 = *reinterpret_cast<const float4*>(Ap);
    float4 ra1 = *reinterpret_cast<const float4*>(Ap + 4);
    float4 rb0 = *reinterpret_cast<const float4*>(Bp);
    float4 rb1 = *reinterpret_cast<const float4*>(Bp + 64);

    {
        As[0][(akc + 0) * SK_ + arow] = f2tf32(ra0.x);
        As[0][(akc + 1) * SK_ + arow] = f2tf32(ra0.y);
        As[0][(akc + 2) * SK_ + arow] = f2tf32(ra0.z);
        As[0][(akc + 3) * SK_ + arow] = f2tf32(ra0.w);
        As[0][(akc + 4) * SK_ + arow] = f2tf32(ra1.x);
        As[0][(akc + 5) * SK_ + arow] = f2tf32(ra1.y);
        As[0][(akc + 6) * SK_ + arow] = f2tf32(ra1.z);
        As[0][(akc + 7) * SK_ + arow] = f2tf32(ra1.w);
        int bb = bkt * 4 + bqk;
        Bs[0][((bnc + 0) * BSTR_ + bb) * 2 + bkhi] = f2tf32(rb0.x);
        Bs[0][((bnc + 1) * BSTR_ + bb) * 2 + bkhi] = f2tf32(rb0.y);
        Bs[0][((bnc + 2) * BSTR_ + bb) * 2 + bkhi] = f2tf32(rb0.z);
        Bs[0][((bnc + 3) * BSTR_ + bb) * 2 + bkhi] = f2tf32(rb0.w);
        Bs[0][((bnc + 64) * BSTR_ + bb) * 2 + bkhi] = f2tf32(rb1.x);
        Bs[0][((bnc + 65) * BSTR_ + bb) * 2 + bkhi] = f2tf32(rb1.y);
        Bs[0][((bnc + 66) * BSTR_ + bb) * 2 + bkhi] = f2tf32(rb1.z);
        Bs[0][((bnc + 67) * BSTR_ + bb) * 2 + bkhi] = f2tf32(rb1.w);
    }
    __syncthreads();

    const int ntiles = K / 16;
    for (int it = 0; it < ntiles; it++) {
        const int s = it & 1;

        // issue next tile's global loads (overlap with compute)
        if (it + 1 < ntiles) {
            Ap += 16;
            Bp += (size_t)16 * N;
            ra0 = *reinterpret_cast<const float4*>(Ap);
            ra1 = *reinterpret_cast<const float4*>(Ap + 4);
            rb0 = *reinterpret_cast<const float4*>(Bp);
            rb1 = *reinterpret_cast<const float4*>(Bp + 64);
        }

        // compute over stage s
        #pragma unroll
        for (int kt = 0; kt < 2; kt++) {
            const int ksb = kt * 8;
            unsigned af[2][4];
            #pragma unroll
            for (int mf = 0; mf < 2; mf++) {
                int m = wm + mf * 16 + qm;
                af[mf][0] = As[s][(ksb + qk)     * SK_ + m];
                af[mf][1] = As[s][(ksb + qk)     * SK_ + m + 8];
                af[mf][2] = As[s][(ksb + qk + 4) * SK_ + m];
                af[mf][3] = As[s][(ksb + qk + 4) * SK_ + m + 8];
            }
            uint2 bf[8];
            #pragma unroll
            for (int nf = 0; nf < 8; nf++) {
                int n = wn + nf * 8 + qm;
                bf[nf] = *reinterpret_cast<const uint2*>(
                    &Bs[s][(n * BSTR_ + kt * 4 + qk) * 2]);
            }
            #pragma unroll
            for (int mf = 0; mf < 2; mf++)
                #pragma unroll
                for (int nf = 0; nf < 8; nf++)
                    mma_tf32(acc[mf][nf], af[mf][0], af[mf][1], af[mf][2], af[mf][3],
                             bf[nf].x, bf[nf].y);
        }

        // store next tile into the other stage
        if (it + 1 < ntiles) {
            const int d = s ^ 1;
            As[d][(akc + 0) * SK_ + arow] = f2tf32(ra0.x);
            As[d][(akc + 1) * SK_ + arow] = f2tf32(ra0.y);
            As[d][(akc + 2) * SK_ + arow] = f2tf32(ra0.z);
            As[d][(akc + 3) * SK_ + arow] = f2tf32(ra0.w);
            As[d][(akc + 4) * SK_ + arow] = f2tf32(ra1.x);
            As[d][(akc + 5) * SK_ + arow] = f2tf32(ra1.y);
            As[d][(akc + 6) * SK_ + arow] = f2tf32(ra1.z);
            As[d][(akc + 7) * SK_ + arow] = f2tf32(ra1.w);
            int bb = bkt * 4 + bqk;
            Bs[d][((bnc + 0) * BSTR_ + bb) * 2 + bkhi] = f2tf32(rb0.x);
            Bs[d][((bnc + 1) * BSTR_ + bb) * 2 + bkhi] = f2tf32(rb0.y);
            Bs[d][((bnc + 2) * BSTR_ + bb) * 2 + bkhi] = f2tf32(rb0.z);
            Bs[d][((bnc + 3) * BSTR_ + bb) * 2 + bkhi] = f2tf32(rb0.w);
            Bs[d][((bnc + 64) * BSTR_ + bb) * 2 + bkhi] = f2tf32(rb1.x);
            Bs[d][((bnc + 65) * BSTR_ + bb) * 2 + bkhi] = f2tf32(rb1.y);
            Bs[d][((bnc + 66) * BSTR_ + bb) * 2 + bkhi] = f2tf32(rb1.z);
            Bs[d][((bnc + 67) * BSTR_ + bb) * 2 + bkhi] = f2tf32(rb1.w);
        }
        __syncthreads();
    }

    // epilogue
    #pragma unroll
    for (int mf = 0; mf < 2; mf++) {
        int row0 = bm + wm + mf * 16 + qm;
        #pragma unroll
        for (int nf = 0; nf < 8; nf++) {
            int col = bn + wn + nf * 8 + 2 * qk;
            size_t off0 = (size_t)row0 * N + col;
            size_t off1 = (size_t)(row0 + 8) * N + col;
            float2 o0 = make_float2(acc[mf][nf][0], acc[mf][nf][1]);
            float2 o1 = make_float2(acc[mf][nf][2], acc[mf][nf][3]);
            if (RES) {
                float2 r0 = *reinterpret_cast<const float2*>(R + off0);
                float2 r1 = *reinterpret_cast<const float2*>(R + off1);
                o0.x += r0.x; o0.y += r0.y;
                o1.x += r1.x; o1.y += r1.y;
            }
            *reinterpret_cast<float2*>(C + off0) = o0;
            *reinterpret_cast<float2*>(C + off1) = o1;
        }
    }
}

// ---------------------------------------------------------------------------
// Flash attention (causal): grid = (T/64, B*H), 256 threads.
// ---------------------------------------------------------------------------
#define ATTN_SMEM ((64 * 64 + 64 * 65 + 64 * 64) * 4)

__global__ void __launch_bounds__(256)
attn_kernel(const float* __restrict__ Q, const float* __restrict__ K,
            const float* __restrict__ V, float* __restrict__ O)
{
    extern __shared__ float sm[];
    float* Qs  = sm;                 // [64][64]
    float* Kts = sm + 64 * 64;       // [64][65]  (transposed K; aliased as P)
    float* Vs  = Kts + 64 * 65;      // [64][64]

    int tid = threadIdx.x;
    int ty = tid >> 4, tx = tid & 15;
    int b = blockIdx.y >> 4, h = blockIdx.y & 15;
    int qb = blockIdx.x * 64;

    const float* Qb = Q + (size_t)b * T_ * D_ + h * HD_;
    const float* Kb = K + (size_t)b * T_ * D_ + h * HD_;
    const float* Vb = V + (size_t)b * T_ * D_ + h * HD_;

    int ltok = tid >> 4;
    int ld0  = (tid & 15) * 4;

    #pragma unroll
    for (int rep = 0; rep < 4; rep++) {
        int t = rep * 16 + ltok;
        float4 qv = *reinterpret_cast<const float4*>(Qb + (size_t)(qb + t) * D_ + ld0);
        *reinterpret_cast<float4*>(&Qs[t * 64 + ld0]) = qv;
    }

    float acc[4][4];
    float m_i[4], l_i[4];
    #pragma unroll
    for (int i = 0; i < 4; i++) {
        m_i[i] = -1e30f; l_i[i] = 0.f;
        #pragma unroll
        for (int j = 0; j < 4; j++) acc[i][j] = 0.f;
    }

    int ntile = blockIdx.x + 1;
    for (int j = 0; j < ntile; j++) {
        int jb = j * 64;
        __syncthreads();
        #pragma unroll
        for (int rep = 0; rep < 4; rep++) {
            int t = rep * 16 + ltok;
            float4 kv = *reinterpret_cast<const float4*>(Kb + (size_t)(jb + t) * D_ + ld0);
            Kts[(ld0 + 0) * 65 + t] = kv.x;
            Kts[(ld0 + 1) * 65 + t] = kv.y;
            Kts[(ld0 + 2) * 65 + t] = kv.z;
            Kts[(ld0 + 3) * 65 + t] = kv.w;
            float4 vv = *reinterpret_cast<const float4*>(Vb + (size_t)(jb + t) * D_ + ld0);
            *reinterpret_cast<float4*>(&Vs[t * 64 + ld0]) = vv;
        }
        __syncthreads();

        float s[4][4];
        #pragma unroll
        for (int i = 0; i < 4; i++)
            #pragma unroll
            for (int jj = 0; jj < 4; jj++) s[i][jj] = 0.f;

        #pragma unroll 4
        for (int d = 0; d < 64; d++) {
            float a0 = Qs[(ty * 4 + 0) * 64 + d];
            float a1 = Qs[(ty * 4 + 1) * 64 + d];
            float a2 = Qs[(ty * 4 + 2) * 64 + d];
            float a3 = Qs[(ty * 4 + 3) * 64 + d];
            float b0 = Kts[d * 65 + tx * 4 + 0];
            float b1 = Kts[d * 65 + tx * 4 + 1];
            float b2 = Kts[d * 65 + tx * 4 + 2];
            float b3 = Kts[d * 65 + tx * 4 + 3];
            s[0][0] += a0 * b0; s[0][1] += a0 * b1; s[0][2] += a0 * b2; s[0][3] += a0 * b3;
            s[1][0] += a1 * b0; s[1][1] += a1 * b1; s[1][2] += a1 * b2; s[1][3] += a1 * b3;
            s[2][0] += a2 * b0; s[2][1] += a2 * b1; s[2][2] += a2 * b2; s[2][3] += a2 * b3;
            s[3][0] += a3 * b0; s[3][1] += a3 * b1; s[3][2] += a3 * b2; s[3][3] += a3 * b3;
        }

        bool diag = (jb == qb);
        #pragma unroll
        for (int i = 0; i < 4; i++)
            #pragma unroll
            for (int jj = 0; jj < 4; jj++) {
                float sv = s[i][jj] * 0.125f;
                if (diag && (tx * 4 + jj > ty * 4 + i)) sv = -1e30f;
                s[i][jj] = sv;
            }

        __syncthreads();

        #pragma unroll
        for (int i = 0; i < 4; i++) {
            float mx = fmaxf(fmaxf(s[i][0], s[i][1]), fmaxf(s[i][2], s[i][3]));
            #pragma unroll
            for (int o = 1; o < 16; o <<= 1) mx = fmaxf(mx, __shfl_xor_sync(0xffffffffu, mx, o));
            float mn = fmaxf(m_i[i], mx);
            float p0 = __expf(s[i][0] - mn);
            float p1 = __expf(s[i][1] - mn);
            float p2 = __expf(s[i][2] - mn);
            float p3 = __expf(s[i][3] - mn);
            float sum = p0 + p1 + p2 + p3;
            #pragma unroll
            for (int o = 1; o < 16; o <<= 1) sum += __shfl_xor_sync(0xffffffffu, sum, o);
            float al = __expf(m_i[i] - mn);
            l_i[i] = l_i[i] * al + sum;
            m_i[i] = mn;
            acc[i][0] *= al; acc[i][1] *= al; acc[i][2] *= al; acc[i][3] *= al;
            float* Ps = Kts;
            Ps[(ty * 4 + i) * 65 + tx * 4 + 0] = p0;
            Ps[(ty * 4 + i) * 65 + tx * 4 + 1] = p1;
            Ps[(ty * 4 + i) * 65 + tx * 4 + 2] = p2;
            Ps[(ty * 4 + i) * 65 + tx * 4 + 3] = p3;
        }
        __syncthreads();

        #pragma unroll 4
        for (int c = 0; c < 64; c++) {
            float p0 = Kts[(ty * 4 + 0) * 65 + c];
            float p1 = Kts[(ty * 4 + 1) * 65 + c];
            float p2 = Kts[(ty * 4 + 2) * 65 + c];
            float p3 = Kts[(ty * 4 + 3) * 65 + c];
            float4 vv = *reinterpret_cast<const float4*>(&Vs[c * 64 + tx * 4]);
            acc[0][0] += p0 * vv.x; acc[0][1] += p0 * vv.y; acc[0][2] += p0 * vv.z; acc[0][3] += p0 * vv.w;
            acc[1][0] += p1 * vv.x; acc[1][1] += p1 * vv.y; acc[1][2] += p1 * vv.z; acc[1][3] += p1 * vv.w;
            acc[2][0] += p2 * vv.x; acc[2][1] += p2 * vv.y; acc[2][2] += p2 * vv.z; acc[2][3] += p2 * vv.w;
            acc[3][0] += p3 * vv.x; acc[3][1] += p3 * vv.y; acc[3][2] += p3 * vv.z; acc[3][3] += p3 * vv.w;
        }
    }

    #pragma unroll
    for (int i = 0; i < 4; i++) {
        float inv = 1.0f / l_i[i];
        float4 o = make_float4(acc[i][0] * inv, acc[i][1] * inv,
                               acc[i][2] * inv, acc[i][3] * inv);
        *reinterpret_cast<float4*>(const_cast<float*>(
            O + (size_t)b * T_ * D_ + h * HD_ + (size_t)(qb + ty * 4 + i) * D_ + tx * 4)) = o;
    }
}

// ---------------------------------------------------------------------------
// a = silu(a) * g  (elementwise, float4)
// ---------------------------------------------------------------------------
__global__ void silu_mul_kernel(float* __restrict__ a, const float* __restrict__ g)
{
    int i = blockIdx.x * blockDim.x + threadIdx.x;
    float4 av = reinterpret_cast<float4*>(a)[i];
    float4 gv = reinterpret_cast<const float4*>(g)[i];
    av.x = av.x / (1.f + __expf(-av.x)) * gv.x;
    av.y = av.y / (1.f + __expf(-av.y)) * gv.y;
    av.z = av.z / (1.f + __expf(-av.z)) * gv.z;
    av.w = av.w / (1.f + __expf(-av.w)) * gv.w;
    reinterpret_cast<float4*>(a)[i] = av;
}

// ---------------------------------------------------------------------------
// Orchestration
// ---------------------------------------------------------------------------
extern "C" void kernel_launch(void* const* d_in, const int* in_sizes, int n_in,
                              void* d_out, int out_size)
{
    const float* h    = (const float*)d_in[0];
    const float* alng = (const float*)d_in[2];
    const float* alnb = (const float*)d_in[3];
    const float* mlng = (const float*)d_in[4];
    const float* mlnb = (const float*)d_in[5];
    const float* wq   = (const float*)d_in[6];
    const float* wk   = (const float*)d_in[7];
    const float* wv   = (const float*)d_in[8];
    const float* wo   = (const float*)d_in[9];
    const float* w1   = (const float*)d_in[10];
    const float* w2   = (const float*)d_in[11];
    const float* wout = (const float*)d_in[12];
    float* out = (float*)d_out;

    float *px, *pq, *pk, *pv, *po, *ph2, *py, *pa, *pg;
    cudaGetSymbolAddress((void**)&px,  g_x);
    cudaGetSymbolAddress((void**)&pq,  g_q);
    cudaGetSymbolAddress((void**)&pk,  g_k);
    cudaGetSymbolAddress((void**)&pv,  g_v);
    cudaGetSymbolAddress((void**)&po,  g_o);
    cudaGetSymbolAddress((void**)&ph2, g_h2);
    cudaGetSymbolAddress((void**)&py,  g_y);
    cudaGetSymbolAddress((void**)&pa,  g_a);
    cudaGetSymbolAddress((void**)&pg,  g_g);
    cudaFuncSetAttribute(attn_kernel, cudaFuncAttributeMaxDynamicSharedMemorySize, ATTN_SMEM);

    dim3 gQKV(D_ / 128, ROWS_ / 128, 3);   // (8, 64, 3)
    dim3 gD(D_ / 128, ROWS_ / 128);        // (8, 64)
    dim3 gF(FFN_ / 128, ROWS_ / 128);      // (32, 64)

    // x = LN(h)
    ln_kernel<<<ROWS_, 256>>>(h, alng, alnb, px);
    // q,k,v = x @ {wq,wk,wv}   (fused launch)
    tgemm_kernel<false, 3><<<gQKV, 256>>>(px, wq, wk, wv, nullptr,
                                          pq, pk, pv, ROWS_, D_, D_);
    // o = attention(q,k,v)
    attn_kernel<<<dim3(T_ / 64, B_ * H_), 256, ATTN_SMEM>>>(pq, pk, pv, po);
    // h2 = h + o @ wo
    tgemm_kernel<true, 1><<<gD, 256>>>(po, wo, nullptr, nullptr, h,
                                       ph2, nullptr, nullptr, ROWS_, D_, D_);
    // y = LN(h2)
    ln_kernel<<<ROWS_, 256>>>(ph2, mlng, mlnb, py);
    // a = y@w1 ; g = y@w2
    tgemm_kernel<false, 1><<<gF, 256>>>(py, w1, nullptr, nullptr, nullptr,
                                        pa, nullptr, nullptr, ROWS_, FFN_, D_);
    tgemm_kernel<false, 1><<<gF, 256>>>(py, w2, nullptr, nullptr, nullptr,
                                        pg, nullptr, nullptr, ROWS_, FFN_, D_);
    // a = silu(a)*g
    silu_mul_kernel<<<(ROWS_ * FFN_ / 4) / 256, 256>>>(pa, pg);
    // out = h2 + a @ wout
    tgemm_kernel<true, 1><<<gD, 256>>>(pa, wout, nullptr, nullptr, ph2,
                                       out, nullptr, nullptr, ROWS_, D_, FFN_);
}

// round 5
// speedup vs baseline: 1.2676x; 1.2676x over previous
#include <cuda_runtime.h>
#include <math.h>

// Problem constants
#define B_    4
#define T_    2048
#define D_    1024
#define H_    16
#define HD_   64
#define FFN_  4096
#define ROWS_ (B_ * T_)        // 8192

// ---------------------------------------------------------------------------
// Scratch (device globals -- allocation inside kernel_launch is forbidden)
// ---------------------------------------------------------------------------
__device__ float g_x [ROWS_ * D_];    // LN1 output (tf32-rounded)
__device__ float g_q [ROWS_ * D_];
__device__ float g_k [ROWS_ * D_];
__device__ float g_v [ROWS_ * D_];
__device__ float g_o [ROWS_ * D_];    // attention output (tf32-rounded)
__device__ float g_h2[ROWS_ * D_];    // h + o@wo (full fp32)
__device__ float g_y [ROWS_ * D_];    // LN2 output (tf32-rounded)
__device__ float g_a [ROWS_ * FFN_];  // y@w1 (then tf32(silu(a)*g) in place)
__device__ float g_g [ROWS_ * FFN_];  // y@w2

// tf32-rounded weight copies
__device__ float g_wq [D_ * D_];
__device__ float g_wk [D_ * D_];
__device__ float g_wv [D_ * D_];
__device__ float g_wo [D_ * D_];
__device__ float g_w1 [D_ * FFN_];
__device__ float g_w2 [D_ * FFN_];
__device__ float g_wout[FFN_ * D_];

// ---------------------------------------------------------------------------
// Helpers
// ---------------------------------------------------------------------------
__device__ __forceinline__ float f2tf32f(float x) {
    unsigned u;
    asm("cvt.rna.tf32.f32 %0, %1;" : "=r"(u) : "f"(x));
    return __uint_as_float(u);
}

__device__ __forceinline__ void mma_tf32(float c[4],
                                         unsigned a0, unsigned a1, unsigned a2, unsigned a3,
                                         unsigned b0, unsigned b1) {
    asm volatile(
        "mma.sync.aligned.m16n8k8.row.col.f32.tf32.tf32.f32 "
        "{%0,%1,%2,%3}, {%4,%5,%6,%7}, {%8,%9}, {%0,%1,%2,%3};"
        : "+f"(c[0]), "+f"(c[1]), "+f"(c[2]), "+f"(c[3])
        : "r"(a0), "r"(a1), "r"(a2), "r"(a3), "r"(b0), "r"(b1));
}

__device__ __forceinline__ void cp16(unsigned dst, const void* src) {
    asm volatile("cp.async.cg.shared.global [%0], [%1], 16;" :: "r"(dst), "l"(src));
}
#define CP_COMMIT() asm volatile("cp.async.commit_group;" ::: "memory")
template <int N> __device__ __forceinline__ void cp_wait() {
    asm volatile("cp.async.wait_group %0;" :: "n"(N) : "memory");
}

// ---------------------------------------------------------------------------
// Round a buffer to tf32 (for weights)
// ---------------------------------------------------------------------------
__global__ void round_kernel(const float* __restrict__ in, float* __restrict__ out)
{
    int i = blockIdx.x * blockDim.x + threadIdx.x;
    float4 v = reinterpret_cast<const float4*>(in)[i];
    v.x = f2tf32f(v.x); v.y = f2tf32f(v.y);
    v.z = f2tf32f(v.z); v.w = f2tf32f(v.w);
    reinterpret_cast<float4*>(out)[i] = v;
}

// ---------------------------------------------------------------------------
// LayerNorm: one block (256 threads) per row of 1024; output tf32-rounded
// ---------------------------------------------------------------------------
__global__ void ln_kernel(const float* __restrict__ in,
                          const float* __restrict__ gam,
                          const float* __restrict__ bet,
                          float* __restrict__ out)
{
    __shared__ float r1[8], r2[8];
    __shared__ float s_mu, s_rstd;
    int row = blockIdx.x, tid = threadIdx.x;

    const float4* p = reinterpret_cast<const float4*>(in) + (size_t)row * (D_ / 4);
    float4 v = p[tid];
    float s  = v.x + v.y + v.z + v.w;
    float s2 = v.x * v.x + v.y * v.y + v.z * v.z + v.w * v.w;
    #pragma unroll
    for (int o = 16; o; o >>= 1) {
        s  += __shfl_xor_sync(0xffffffffu, s,  o);
        s2 += __shfl_xor_sync(0xffffffffu, s2, o);
    }
    if ((tid & 31) == 0) { r1[tid >> 5] = s; r2[tid >> 5] = s2; }
    __syncthreads();
    if (tid == 0) {
        float a = 0.f, b = 0.f;
        #pragma unroll
        for (int i = 0; i < 8; i++) { a += r1[i]; b += r2[i]; }
        float mu  = a / (float)D_;
        float var = b / (float)D_ - mu * mu;
        s_mu = mu;
        s_rstd = rsqrtf(var + 1e-5f);
    }
    __syncthreads();
    float mu = s_mu, rs = s_rstd;
    float4 g4 = reinterpret_cast<const float4*>(gam)[tid];
    float4 b4 = reinterpret_cast<const float4*>(bet)[tid];
    float4 o;
    o.x = f2tf32f((v.x - mu) * rs * g4.x + b4.x);
    o.y = f2tf32f((v.y - mu) * rs * g4.y + b4.y);
    o.z = f2tf32f((v.z - mu) * rs * g4.z + b4.z);
    o.w = f2tf32f((v.w - mu) * rs * g4.w + b4.w);
    reinterpret_cast<float4*>(out)[(size_t)row * (D_ / 4) + tid] = o;
}

// ---------------------------------------------------------------------------
// TF32 tensor-core GEMM, 3-stage cp.async pipeline.
// C[M,N] = A[M,K] @ W[K,N] (+R). Block 128x128, BK=16, 8 warps (4m x 2n),
// warp tile 32x64 via mma.m16n8k8 (2 mf x 8 nf).
// A smem: [m][k] rows of 16, stride 20 floats (conflict-free frag reads).
// B smem: [k][n] rows of 128, stride 136 floats (conflict-free frag reads).
// Inputs must be pre-rounded to tf32 (raw bits consumed as tf32).
// NGEM selects W/C by blockIdx.z (QKV fusion).
// ---------------------------------------------------------------------------
#define AST_ 20
#define BST_ 136
#define ATILE_ (128 * AST_)   // floats per A stage
#define BTILE_ (16 * BST_)    // floats per B stage
#define GEMM_SMEM (3 * (ATILE_ + BTILE_) * 4)

template <bool RES, int NGEM>
__global__ void __launch_bounds__(256, 2)
tgemm_kernel(const float* __restrict__ A,
             const float* __restrict__ W0, const float* __restrict__ W1,
             const float* __restrict__ W2,
             const float* __restrict__ R,
             float* __restrict__ C0, float* __restrict__ C1, float* __restrict__ C2,
             int M, int N, int K)
{
    extern __shared__ float sm[];
    float* As = sm;                    // [3][ATILE_]
    float* Bs = sm + 3 * ATILE_;       // [3][BTILE_]

    const float* W = W0;
    float* C = C0;
    if (NGEM == 3) {
        int z = blockIdx.z;
        W = (z == 0) ? W0 : (z == 1) ? W1 : W2;
        C = (z == 0) ? C0 : (z == 1) ? C1 : C2;
    }

    const int tid  = threadIdx.x;
    const int lane = tid & 31;
    const int warp = tid >> 5;
    const int wm   = (warp >> 1) * 32;   // warp m-offset
    const int wn   = (warp & 1) * 64;    // warp n-offset
    const int qm   = lane >> 2;          // 0..7
    const int qk   = lane & 3;           // 0..3

    const int bm = blockIdx.y * 128, bn = blockIdx.x * 128;

    // cp.async assignments (4 x 16B per thread per tile: 2 A chunks, 2 B chunks)
    const int arow0 = tid >> 2;          // 0..63  (and +64)
    const int aseg  = (tid & 3) * 4;     // float offset 0,4,8,12
    const int brow0 = tid >> 5;          // 0..7   (and +8)
    const int bseg  = (tid & 31) * 4;    // float offset 0..124

    const float* Abase = A + (size_t)bm * K;
    const float* Wbase = W + bn;

    float acc[2][8][4];
    #pragma unroll
    for (int i = 0; i < 2; i++)
        #pragma unroll
        for (int j = 0; j < 8; j++)
            #pragma unroll
            for (int r = 0; r < 4; r++) acc[i][j][r] = 0.f;

    auto issue_tile = [&](int kt, int st) {
        unsigned abase = (unsigned)__cvta_generic_to_shared(&As[st * ATILE_]);
        unsigned bbase = (unsigned)__cvta_generic_to_shared(&Bs[st * BTILE_]);
        const float* Ag = Abase + kt * 16;
        const float* Bg = Wbase + (size_t)(kt * 16) * N;
        cp16(abase + (unsigned)(arow0 * AST_ + aseg) * 4,
             Ag + (size_t)arow0 * K + aseg);
        cp16(abase + (unsigned)((arow0 + 64) * AST_ + aseg) * 4,
             Ag + (size_t)(arow0 + 64) * K + aseg);
        cp16(bbase + (unsigned)(brow0 * BST_ + bseg) * 4,
             Bg + (size_t)brow0 * N + bseg);
        cp16(bbase + (unsigned)((brow0 + 8) * BST_ + bseg) * 4,
             Bg + (size_t)(brow0 + 8) * N + bseg);
        CP_COMMIT();
    };

    const int ntiles = K / 16;   // >= 64 here

    // prologue: stages 0 and 1 in flight; wait for stage 0
    issue_tile(0, 0);
    issue_tile(1, 1);
    cp_wait<1>();
    __syncthreads();

    for (int it = 0; it < ntiles; it++) {
        const int s = it % 3;

        // keep 2 tiles in flight
        if (it + 2 < ntiles) issue_tile(it + 2, (it + 2) % 3);

        const float* Asb = &As[s * ATILE_];
        const float* Bsb = &Bs[s * BTILE_];

        #pragma unroll
        for (int kt = 0; kt < 2; kt++) {
            const int ksb = kt * 8;
            unsigned af[2][4];
            #pragma unroll
            for (int mf = 0; mf < 2; mf++) {
                int m = wm + mf * 16 + qm;
                af[mf][0] = __float_as_uint(Asb[(size_t)m * AST_ + ksb + qk]);
                af[mf][1] = __float_as_uint(Asb[(size_t)(m + 8) * AST_ + ksb + qk]);
                af[mf][2] = __float_as_uint(Asb[(size_t)m * AST_ + ksb + qk + 4]);
                af[mf][3] = __float_as_uint(Asb[(size_t)(m + 8) * AST_ + ksb + qk + 4]);
            }
            unsigned bf[8][2];
            #pragma unroll
            for (int nf = 0; nf < 8; nf++) {
                int n = wn + nf * 8 + qm;
                bf[nf][0] = __float_as_uint(Bsb[(size_t)(ksb + qk) * BST_ + n]);
                bf[nf][1] = __float_as_uint(Bsb[(size_t)(ksb + qk + 4) * BST_ + n]);
            }
            #pragma unroll
            for (int mf = 0; mf < 2; mf++)
                #pragma unroll
                for (int nf = 0; nf < 8; nf++)
                    mma_tf32(acc[mf][nf], af[mf][0], af[mf][1], af[mf][2], af[mf][3],
                             bf[nf][0], bf[nf][1]);
        }

        // ensure next stage's tile has landed before anyone computes on it;
        // sync also protects the stage we will overwrite next iteration.
        if (it + 2 < ntiles)       cp_wait<1>();
        else if (it + 1 < ntiles)  cp_wait<0>();
        __syncthreads();
    }

    // epilogue: c0,c1 -> (row, 2qk..2qk+1), c2,c3 -> (row+8, same cols)
    #pragma unroll
    for (int mf = 0; mf < 2; mf++) {
        int row0 = bm + wm + mf * 16 + qm;
        #pragma unroll
        for (int nf = 0; nf < 8; nf++) {
            int col = bn + wn + nf * 8 + 2 * qk;
            size_t off0 = (size_t)row0 * N + col;
            size_t off1 = (size_t)(row0 + 8) * N + col;
            float2 o0 = make_float2(acc[mf][nf][0], acc[mf][nf][1]);
            float2 o1 = make_float2(acc[mf][nf][2], acc[mf][nf][3]);
            if (RES) {
                float2 r0 = *reinterpret_cast<const float2*>(R + off0);
                float2 r1 = *reinterpret_cast<const float2*>(R + off1);
                o0.x += r0.x; o0.y += r0.y;
                o1.x += r1.x; o1.y += r1.y;
            }
            *reinterpret_cast<float2*>(C + off0) = o0;
            *reinterpret_cast<float2*>(C + off1) = o1;
        }
    }
}

// ---------------------------------------------------------------------------
// Flash attention (causal): grid = (T/64, B*H), 256 threads.
// Output tf32-rounded (feeds wo GEMM).
// ---------------------------------------------------------------------------
#define ATTN_SMEM ((64 * 64 + 64 * 65 + 64 * 64) * 4)

__global__ void __launch_bounds__(256)
attn_kernel(const float* __restrict__ Q, const float* __restrict__ K,
            const float* __restrict__ V, float* __restrict__ O)
{
    extern __shared__ float smf[];
    float* Qs  = smf;                // [64][64]
    float* Kts = smf + 64 * 64;      // [64][65]  (transposed K; aliased as P)
    float* Vs  = Kts + 64 * 65;      // [64][64]

    int tid = threadIdx.x;
    int ty = tid >> 4, tx = tid & 15;
    int b = blockIdx.y >> 4, h = blockIdx.y & 15;
    int qb = blockIdx.x * 64;

    const float* Qb = Q + (size_t)b * T_ * D_ + h * HD_;
    const float* Kb = K + (size_t)b * T_ * D_ + h * HD_;
    const float* Vb = V + (size_t)b * T_ * D_ + h * HD_;

    int ltok = tid >> 4;
    int ld0  = (tid & 15) * 4;

    #pragma unroll
    for (int rep = 0; rep < 4; rep++) {
        int t = rep * 16 + ltok;
        float4 qv = *reinterpret_cast<const float4*>(Qb + (size_t)(qb + t) * D_ + ld0);
        *reinterpret_cast<float4*>(&Qs[t * 64 + ld0]) = qv;
    }

    float acc[4][4];
    float m_i[4], l_i[4];
    #pragma unroll
    for (int i = 0; i < 4; i++) {
        m_i[i] = -1e30f; l_i[i] = 0.f;
        #pragma unroll
        for (int j = 0; j < 4; j++) acc[i][j] = 0.f;
    }

    int ntile = blockIdx.x + 1;
    for (int j = 0; j < ntile; j++) {
        int jb = j * 64;
        __syncthreads();
        #pragma unroll
        for (int rep = 0; rep < 4; rep++) {
            int t = rep * 16 + ltok;
            float4 kv = *reinterpret_cast<const float4*>(Kb + (size_t)(jb + t) * D_ + ld0);
            Kts[(ld0 + 0) * 65 + t] = kv.x;
            Kts[(ld0 + 1) * 65 + t] = kv.y;
            Kts[(ld0 + 2) * 65 + t] = kv.z;
            Kts[(ld0 + 3) * 65 + t] = kv.w;
            float4 vv = *reinterpret_cast<const float4*>(Vb + (size_t)(jb + t) * D_ + ld0);
            *reinterpret_cast<float4*>(&Vs[t * 64 + ld0]) = vv;
        }
        __syncthreads();

        float s[4][4];
        #pragma unroll
        for (int i = 0; i < 4; i++)
            #pragma unroll
            for (int jj = 0; jj < 4; jj++) s[i][jj] = 0.f;

        #pragma unroll 4
        for (int d = 0; d < 64; d++) {
            float a0 = Qs[(ty * 4 + 0) * 64 + d];
            float a1 = Qs[(ty * 4 + 1) * 64 + d];
            float a2 = Qs[(ty * 4 + 2) * 64 + d];
            float a3 = Qs[(ty * 4 + 3) * 64 + d];
            float b0 = Kts[d * 65 + tx * 4 + 0];
            float b1 = Kts[d * 65 + tx * 4 + 1];
            float b2 = Kts[d * 65 + tx * 4 + 2];
            float b3 = Kts[d * 65 + tx * 4 + 3];
            s[0][0] += a0 * b0; s[0][1] += a0 * b1; s[0][2] += a0 * b2; s[0][3] += a0 * b3;
            s[1][0] += a1 * b0; s[1][1] += a1 * b1; s[1][2] += a1 * b2; s[1][3] += a1 * b3;
            s[2][0] += a2 * b0; s[2][1] += a2 * b1; s[2][2] += a2 * b2; s[2][3] += a2 * b3;
            s[3][0] += a3 * b0; s[3][1] += a3 * b1; s[3][2] += a3 * b2; s[3][3] += a3 * b3;
        }

        bool diag = (jb == qb);
        #pragma unroll
        for (int i = 0; i < 4; i++)
            #pragma unroll
            for (int jj = 0; jj < 4; jj++) {
                float sv = s[i][jj] * 0.125f;
                if (diag && (tx * 4 + jj > ty * 4 + i)) sv = -1e30f;
                s[i][jj] = sv;
            }

        __syncthreads();

        #pragma unroll
        for (int i = 0; i < 4; i++) {
            float mx = fmaxf(fmaxf(s[i][0], s[i][1]), fmaxf(s[i][2], s[i][3]));
            #pragma unroll
            for (int o = 1; o < 16; o <<= 1) mx = fmaxf(mx, __shfl_xor_sync(0xffffffffu, mx, o));
            float mn = fmaxf(m_i[i], mx);
            float p0 = __expf(s[i][0] - mn);
            float p1 = __expf(s[i][1] - mn);
            float p2 = __expf(s[i][2] - mn);
            float p3 = __expf(s[i][3] - mn);
            float sum = p0 + p1 + p2 + p3;
            #pragma unroll
            for (int o = 1; o < 16; o <<= 1) sum += __shfl_xor_sync(0xffffffffu, sum, o);
            float al = __expf(m_i[i] - mn);
            l_i[i] = l_i[i] * al + sum;
            m_i[i] = mn;
            acc[i][0] *= al; acc[i][1] *= al; acc[i][2] *= al; acc[i][3] *= al;
            float* Ps = Kts;
            Ps[(ty * 4 + i) * 65 + tx * 4 + 0] = p0;
            Ps[(ty * 4 + i) * 65 + tx * 4 + 1] = p1;
            Ps[(ty * 4 + i) * 65 + tx * 4 + 2] = p2;
            Ps[(ty * 4 + i) * 65 + tx * 4 + 3] = p3;
        }
        __syncthreads();

        #pragma unroll 4
        for (int c = 0; c < 64; c++) {
            float p0 = Kts[(ty * 4 + 0) * 65 + c];
            float p1 = Kts[(ty * 4 + 1) * 65 + c];
            float p2 = Kts[(ty * 4 + 2) * 65 + c];
            float p3 = Kts[(ty * 4 + 3) * 65 + c];
            float4 vv = *reinterpret_cast<const float4*>(&Vs[c * 64 + tx * 4]);
            acc[0][0] += p0 * vv.x; acc[0][1] += p0 * vv.y; acc[0][2] += p0 * vv.z; acc[0][3] += p0 * vv.w;
            acc[1][0] += p1 * vv.x; acc[1][1] += p1 * vv.y; acc[1][2] += p1 * vv.z; acc[1][3] += p1 * vv.w;
            acc[2][0] += p2 * vv.x; acc[2][1] += p2 * vv.y; acc[2][2] += p2 * vv.z; acc[2][3] += p2 * vv.w;
            acc[3][0] += p3 * vv.x; acc[3][1] += p3 * vv.y; acc[3][2] += p3 * vv.z; acc[3][3] += p3 * vv.w;
        }
    }

    #pragma unroll
    for (int i = 0; i < 4; i++) {
        float inv = 1.0f / l_i[i];
        float4 o = make_float4(f2tf32f(acc[i][0] * inv), f2tf32f(acc[i][1] * inv),
                               f2tf32f(acc[i][2] * inv), f2tf32f(acc[i][3] * inv));
        *reinterpret_cast<float4*>(const_cast<float*>(
            O + (size_t)b * T_ * D_ + h * HD_ + (size_t)(qb + ty * 4 + i) * D_ + tx * 4)) = o;
    }
}

// ---------------------------------------------------------------------------
// a = tf32(silu(a) * g)  (elementwise, float4; result feeds wout GEMM)
// ---------------------------------------------------------------------------
__global__ void silu_mul_kernel(float* __restrict__ a, const float* __restrict__ g)
{
    int i = blockIdx.x * blockDim.x + threadIdx.x;
    float4 av = reinterpret_cast<float4*>(a)[i];
    float4 gv = reinterpret_cast<const float4*>(g)[i];
    av.x = f2tf32f(av.x / (1.f + __expf(-av.x)) * gv.x);
    av.y = f2tf32f(av.y / (1.f + __expf(-av.y)) * gv.y);
    av.z = f2tf32f(av.z / (1.f + __expf(-av.z)) * gv.z);
    av.w = f2tf32f(av.w / (1.f + __expf(-av.w)) * gv.w);
    reinterpret_cast<float4*>(a)[i] = av;
}

// ---------------------------------------------------------------------------
// Orchestration
// ---------------------------------------------------------------------------
extern "C" void kernel_launch(void* const* d_in, const int* in_sizes, int n_in,
                              void* d_out, int out_size)
{
    const float* h    = (const float*)d_in[0];
    const float* alng = (const float*)d_in[2];
    const float* alnb = (const float*)d_in[3];
    const float* mlng = (const float*)d_in[4];
    const float* mlnb = (const float*)d_in[5];
    const float* wq   = (const float*)d_in[6];
    const float* wk   = (const float*)d_in[7];
    const float* wv   = (const float*)d_in[8];
    const float* wo   = (const float*)d_in[9];
    const float* w1   = (const float*)d_in[10];
    const float* w2   = (const float*)d_in[11];
    const float* wout = (const float*)d_in[12];
    float* out = (float*)d_out;

    float *px, *pq, *pk, *pv, *po, *ph2, *py, *pa, *pg;
    float *rwq, *rwk, *rwv, *rwo, *rw1, *rw2, *rwout;
    cudaGetSymbolAddress((void**)&px,  g_x);
    cudaGetSymbolAddress((void**)&pq,  g_q);
    cudaGetSymbolAddress((void**)&pk,  g_k);
    cudaGetSymbolAddress((void**)&pv,  g_v);
    cudaGetSymbolAddress((void**)&po,  g_o);
    cudaGetSymbolAddress((void**)&ph2, g_h2);
    cudaGetSymbolAddress((void**)&py,  g_y);
    cudaGetSymbolAddress((void**)&pa,  g_a);
    cudaGetSymbolAddress((void**)&pg,  g_g);
    cudaGetSymbolAddress((void**)&rwq,   g_wq);
    cudaGetSymbolAddress((void**)&rwk,   g_wk);
    cudaGetSymbolAddress((void**)&rwv,   g_wv);
    cudaGetSymbolAddress((void**)&rwo,   g_wo);
    cudaGetSymbolAddress((void**)&rw1,   g_w1);
    cudaGetSymbolAddress((void**)&rw2,   g_w2);
    cudaGetSymbolAddress((void**)&rwout, g_wout);

    cudaFuncSetAttribute(attn_kernel, cudaFuncAttributeMaxDynamicSharedMemorySize, ATTN_SMEM);
    cudaFuncSetAttribute(tgemm_kernel<false, 3>, cudaFuncAttributeMaxDynamicSharedMemorySize, GEMM_SMEM);
    cudaFuncSetAttribute(tgemm_kernel<false, 1>, cudaFuncAttributeMaxDynamicSharedMemorySize, GEMM_SMEM);
    cudaFuncSetAttribute(tgemm_kernel<true, 1>,  cudaFuncAttributeMaxDynamicSharedMemorySize, GEMM_SMEM);

    // tf32-round all weights (small BW-bound passes)
    round_kernel<<<(D_ * D_ / 4) / 256, 256>>>(wq, rwq);
    round_kernel<<<(D_ * D_ / 4) / 256, 256>>>(wk, rwk);
    round_kernel<<<(D_ * D_ / 4) / 256, 256>>>(wv, rwv);
    round_kernel<<<(D_ * D_ / 4) / 256, 256>>>(wo, rwo);
    round_kernel<<<(D_ * FFN_ / 4) / 256, 256>>>(w1, rw1);
    round_kernel<<<(D_ * FFN_ / 4) / 256, 256>>>(w2, rw2);
    round_kernel<<<(FFN_ * D_ / 4) / 256, 256>>>(wout, rwout);

    dim3 gQKV(D_ / 128, ROWS_ / 128, 3);   // (8, 64, 3)
    dim3 gD(D_ / 128, ROWS_ / 128);        // (8, 64)
    dim3 gF(FFN_ / 128, ROWS_ / 128);      // (32, 64)

    // x = tf32(LN(h))
    ln_kernel<<<ROWS_, 256>>>(h, alng, alnb, px);
    // q,k,v = x @ {wq,wk,wv}   (fused launch)
    tgemm_kernel<false, 3><<<gQKV, 256, GEMM_SMEM>>>(px, rwq, rwk, rwv, nullptr,
                                                     pq, pk, pv, ROWS_, D_, D_);
    // o = tf32(attention(q,k,v))
    attn_kernel<<<dim3(T_ / 64, B_ * H_), 256, ATTN_SMEM>>>(pq, pk, pv, po);
    // h2 = h + o @ wo
    tgemm_kernel<true, 1><<<gD, 256, GEMM_SMEM>>>(po, rwo, nullptr, nullptr, h,
                                                  ph2, nullptr, nullptr, ROWS_, D_, D_);
    // y = tf32(LN(h2))
    ln_kernel<<<ROWS_, 256>>>(ph2, mlng, mlnb, py);
    // a = y@w1 ; g = y@w2
    tgemm_kernel<false, 1><<<gF, 256, GEMM_SMEM>>>(py, rw1, nullptr, nullptr, nullptr,
                                                   pa, nullptr, nullptr, ROWS_, FFN_, D_);
    tgemm_kernel<false, 1><<<gF, 256, GEMM_SMEM>>>(py, rw2, nullptr, nullptr, nullptr,
                                                   pg, nullptr, nullptr, ROWS_, FFN_, D_);
    // a = tf32(silu(a)*g)
    silu_mul_kernel<<<(ROWS_ * FFN_ / 4) / 256, 256>>>(pa, pg);
    // out = h2 + a @ wout
    tgemm_kernel<true, 1><<<gD, 256, GEMM_SMEM>>>(pa, rwout, nullptr, nullptr, ph2,
                                                  out, nullptr, nullptr, ROWS_, D_, FFN_);
}